// round 13
// baseline (speedup 1.0000x reference)
#include <cuda_runtime.h>
#include <math.h>
#include <stdint.h>

#define TT 512
#define BB 64
#define DD 512
#define HH 512
#define GG 2048
#define KTOT 1024
#define P3_NCTA 128

typedef unsigned long long u64;

// ---------------- device scratch ----------------
__device__ float g_W[(size_t)GG * KTOT];        // 8 MB normalized weights
__device__ float g_h[2][(size_t)BB * HH];       // h double buffer, K-MAJOR: [b][k]
__device__ unsigned g_flagv[P3_NCTA][32];       // per-CTA step flags (128B lines)

// ---------------- f32x2 helpers ----------------
__device__ __forceinline__ void fma2(u64& d, u64 a, u64 b) {
    asm("fma.rn.f32x2 %0, %1, %2, %0;" : "+l"(d) : "l"(a), "l"(b));
}
__device__ __forceinline__ float2 unpack2(u64 v) {
    float2 f; asm("mov.b64 {%0, %1}, %2;" : "=f"(f.x), "=f"(f.y) : "l"(v)); return f;
}

// ---------------- cp.async (L2-only) ----------------
__device__ __forceinline__ void cp_async16(void* smem_dst, const void* gsrc) {
    unsigned s = (unsigned)__cvta_generic_to_shared(smem_dst);
    asm volatile("cp.async.cg.shared.global [%0], [%1], 16;" :: "r"(s), "l"(gsrc));
}
#define CP_COMMIT() asm volatile("cp.async.commit_group;" ::: "memory")
#define CP_WAIT(n)  asm volatile("cp.async.wait_group %0;" :: "n"(n) : "memory")

__device__ __forceinline__ unsigned ld_acq(const unsigned* p) {
    unsigned v;
    asm volatile("ld.acquire.gpu.u32 %0, [%1];" : "=r"(v) : "l"(p) : "memory");
    return v;
}
__device__ __forceinline__ ulonglong2 ldg_nc16(const void* p) {
    ulonglong2 r;
    asm volatile("ld.global.nc.v2.u64 {%0, %1}, [%2];" : "=l"(r.x), "=l"(r.y) : "l"(p));
    return r;
}

__device__ __forceinline__ float sigf(float x) { return 1.0f / (1.0f + expf(-x)); }

// ============================================================================
// Phase 0: per-replay init — zero flags + h buffer 0
// ============================================================================
__global__ __launch_bounds__(256) void qlstm_init() {
    int tid = blockIdx.x * 256 + threadIdx.x;    // grid 128 x 256 = 32768
    ((float*)g_h)[tid] = 0.0f;                   // zeroes g_h[0] exactly
    if (tid < P3_NCTA * 32) ((unsigned*)g_flagv)[tid] = 0u;
}

// ============================================================================
// Phase 1: weight norm
// ============================================================================
__global__ __launch_bounds__(256) void qlstm_wnorm(const float* __restrict__ v,
                                                   const float* __restrict__ g) {
    int r = blockIdx.x;
    const float* vr = v + (size_t)r * KTOT;
    float s = 0.0f;
    for (int k = threadIdx.x; k < KTOT; k += 256) { float x = vr[k]; s += x * x; }
    __shared__ float red[256];
    red[threadIdx.x] = s;
    __syncthreads();
    for (int off = 128; off > 0; off >>= 1) {
        if (threadIdx.x < off) red[threadIdx.x] += red[threadIdx.x + off];
        __syncthreads();
    }
    float scale = g[r] * rsqrtf(red[0]);
    for (int k = threadIdx.x; k < KTOT; k += 256)
        g_W[(size_t)r * KTOT + k] = vr[k] * scale;
}

// ============================================================================
// Phase 3: FUSED persistent recurrence, K-PAIR SIMD (no weight-dup movs).
// Warp = 64-k slice. Thread = 8 rows x 4 batches, acc u64 = (even-k, odd-k).
// x read straight from X[t][b][d] (k-contiguous, L1-reused); h staged k-major.
// ============================================================================
#define HS_BQ_STRIDE 1040                      // bytes; 4*256 + 16 pad (phase-conflict-free)
#define HS_WARP (16 * HS_BQ_STRIDE)            // 16640 B per warp
#define OFF_WX  (16 * 512 * 4)                 // 32768
#define OFF_HS  (OFF_WX + 16 * 512 * 4)        // 65536
#define OFF_ZSP (OFF_HS + 8 * HS_WARP)         // 65536 + 133120 = 198656
#define SM_BYTES (OFF_ZSP + 32768)             // 231424  (< 232448 max)

__global__ __launch_bounds__(256) void qlstm_recur(const float* __restrict__ X,
                                                   const float* __restrict__ bias,
                                                   float* __restrict__ out, int out_size) {
    extern __shared__ unsigned char smraw[];
    float* Whs = (float*)smraw;                     // [16][512] recurrent W
    float* Wxs = (float*)(smraw + OFF_WX);          // [16][512] input W
    unsigned char* hsb = smraw + OFF_HS;            // 8 warps x [16 bq][4 b4][64 k]
    float* zsp = (float*)(smraw + OFF_ZSP);         // [8 ks][16 r][64 b]

    const int tid = threadIdx.x;
    const int bc  = blockIdx.x;
    const int c0  = bc * 4;

    // load both weight slices (rows: lr = gate*4 + (c offset 0..3))
    #pragma unroll
    for (int u = 0; u < 32; u++) {
        int idx = tid + u * 256;
        int lr = idx >> 9, k = idx & 511;
        int gr = (lr >> 2) * 512 + c0 + (lr & 3);
        Whs[lr * 512 + k] = g_W[(size_t)gr * KTOT + 512 + k];
        Wxs[lr * 512 + k] = g_W[(size_t)gr * KTOT + k];
    }

    const int ep_j = tid >> 6, ep_b = tid & 63;
    float bz[4];
    #pragma unroll
    for (int gi = 0; gi < 4; gi++) bz[gi] = bias[gi * 512 + c0 + ep_j];
    float creg = 0.0f, hlast = 0.0f;

    const int ks    = tid >> 5;              // warp k-slice (64 of 512)
    const int lane  = tid & 31;
    const int rg    = lane >> 4;             // 0/1: rows rg*8 .. rg*8+7
    const int bq    = lane & 15;             // batch quad: b = bq*4 .. +3
    const int kbase = ks * 64;
    const unsigned* myflag = &g_flagv[ks * 16 + bq][0];
    const float* whb = Whs + (rg * 8) * 512 + kbase;
    const float* wxb = Wxs + (rg * 8) * 512 + kbase;
    unsigned char* hsw = hsb + ks * HS_WARP;
    const unsigned char* hth = hsw + bq * HS_BQ_STRIDE;
    __syncthreads();

    for (int s = 0; s < TT; s++) {
        u64 acc[8][4];
        #pragma unroll
        for (int j = 0; j < 8; j++)
            #pragma unroll
            for (int b4 = 0; b4 < 4; b4++) acc[j][b4] = 0ULL;

        // ---- x-part: X[t][b][d] k-contiguous; fills the flag-wait window ----
        {
            const float* xb = X + ((size_t)s * BB + bq * 4) * DD + kbase;
            ulonglong2 xq[2][4];
            #pragma unroll
            for (int b4 = 0; b4 < 4; b4++) xq[0][b4] = ldg_nc16(xb + b4 * DD);
            #pragma unroll 4
            for (int kb = 0; kb < 16; kb++) {
                int cur = kb & 1;
                if (kb < 15) {
                    #pragma unroll
                    for (int b4 = 0; b4 < 4; b4++)
                        xq[cur ^ 1][b4] = ldg_nc16(xb + b4 * DD + (kb + 1) * 4);
                }
                #pragma unroll
                for (int j = 0; j < 8; j++) {
                    ulonglong2 wq = *(const ulonglong2*)(wxb + j * 512 + kb * 4);
                    #pragma unroll
                    for (int b4 = 0; b4 < 4; b4++) {
                        fma2(acc[j][b4], wq.x, xq[cur][b4].x);
                        fma2(acc[j][b4], wq.y, xq[cur][b4].y);
                    }
                }
            }
        }

        // ---- per-warp flag wait: the 16 producers of my h k-slice ----
        if (s > 0) {
            for (;;) {
                unsigned v = ld_acq(myflag);
                if (__all_sync(0xFFFFFFFFu, v >= (unsigned)s)) break;
                __nanosleep(20);
            }
        }

        // ---- stage own 16KB h slice, k-major per batch ----
        {
            const float* src = g_h[s & 1] + kbase;
            #pragma unroll
            for (int u = 0; u < 32; u++) {
                int idx = lane + u * 32;               // 0..1023
                int b = idx >> 4, c16 = idx & 15;
                cp_async16(hsw + (b >> 2) * HS_BQ_STRIDE + (b & 3) * 256 + c16 * 16,
                           src + (size_t)b * HH + c16 * 4);
            }
            CP_COMMIT();
            CP_WAIT(0);
            __syncwarp();
        }

        // ---- h-part: accumulate into same registers ----
        #pragma unroll 4
        for (int kb = 0; kb < 16; kb++) {
            ulonglong2 hq[4];
            #pragma unroll
            for (int b4 = 0; b4 < 4; b4++)
                hq[b4] = *(const ulonglong2*)(hth + b4 * 256 + kb * 16);
            #pragma unroll
            for (int j = 0; j < 8; j++) {
                ulonglong2 wq = *(const ulonglong2*)(whb + j * 512 + kb * 4);
                #pragma unroll
                for (int b4 = 0; b4 < 4; b4++) {
                    fma2(acc[j][b4], wq.x, hq[b4].x);
                    fma2(acc[j][b4], wq.y, hq[b4].y);
                }
            }
        }

        // ---- k-split partials (horizontal add of k-pairs) ----
        #pragma unroll
        for (int j = 0; j < 8; j++) {
            int row = rg * 8 + j;
            float4 vals;
            float2 p0 = unpack2(acc[j][0]);
            float2 p1 = unpack2(acc[j][1]);
            float2 p2 = unpack2(acc[j][2]);
            float2 p3 = unpack2(acc[j][3]);
            vals.x = p0.x + p0.y; vals.y = p1.x + p1.y;
            vals.z = p2.x + p2.y; vals.w = p3.x + p3.y;
            *(float4*)&zsp[(ks * 16 + row) * 64 + bq * 4] = vals;
        }
        __syncthreads();

        // ---- gate epilogue ----
        float z[4];
        #pragma unroll
        for (int gi = 0; gi < 4; gi++) {
            int row = gi * 4 + ep_j;
            float ssum = bz[gi];
            #pragma unroll
            for (int q = 0; q < 8; q++)
                ssum += zsp[(q * 16 + row) * 64 + ep_b];
            z[gi] = ssum;
        }
        float fg = sigf(z[0]), ig = sigf(z[1]), ug = tanhf(z[2]), og = sigf(z[3]);
        creg = fg * creg + ig * ug;
        float hv = og * tanhf(creg);
        hlast = hv;
        // publish h k-major: g_h[p][b][col]
        g_h[(s + 1) & 1][(size_t)ep_b * HH + c0 + ep_j] = hv;
        __syncthreads();
        if (tid == 0) {
            __threadfence();
            *(volatile unsigned*)&g_flagv[bc][0] = (unsigned)(s + 1);
        }
        out[((size_t)s * BB + ep_b) * HH + c0 + ep_j] = hv;
    }

    size_t TBH = (size_t)TT * BB * HH;
    if ((size_t)out_size >= TBH + 2 * (size_t)BB * HH) {
        out[TBH + (size_t)ep_b * HH + c0 + ep_j] = hlast;
        out[TBH + (size_t)BB * HH + (size_t)ep_b * HH + c0 + ep_j] = creg;
    }
}

extern "C" void kernel_launch(void* const* d_in, const int* in_sizes, int n_in,
                              void* d_out, int out_size) {
    const float* X  = (const float*)d_in[0];
    const float* v  = (const float*)d_in[1];
    const float* g  = (const float*)d_in[2];
    const float* b  = (const float*)d_in[3];
    float* out = (float*)d_out;

    cudaFuncSetAttribute(qlstm_recur, cudaFuncAttributeMaxDynamicSharedMemorySize, SM_BYTES);

    qlstm_wnorm<<<GG, 256>>>(v, g);
    qlstm_init<<<P3_NCTA, 256>>>();
    qlstm_recur<<<P3_NCTA, 256, SM_BYTES>>>(X, b, out, out_size);
}